// round 11
// baseline (speedup 1.0000x reference)
#include <cuda_runtime.h>
#include <math.h>

#define DINL __device__ __forceinline__
typedef unsigned long long ull;

DINL float silu_f(float x) { return x / (1.f + expf(-x)); }
DINL float sigm_f(float x) { return 1.f / (1.f + expf(-x)); }

DINL void pf_l1(const void* p) { asm volatile("prefetch.global.L1 [%0];" :: "l"(p)); }

// ---------------- packed f32x2 helpers (sm_100+) ----------------
DINL ull pk2(float x) { ull r; asm("mov.b64 %0,{%1,%1};" : "=l"(r) : "f"(x)); return r; }
DINL ull pkpair(float a, float b) { ull r; asm("mov.b64 %0,{%1,%2};" : "=l"(r) : "f"(a), "f"(b)); return r; }
DINL ull f2fma(ull a, ull b, ull c) {
    ull d; asm("fma.rn.f32x2 %0,%1,%2,%3;" : "=l"(d) : "l"(a), "l"(b), "l"(c)); return d;
}
DINL float2 upk(ull a) { float lo, hi; asm("mov.b64 {%0,%1},%2;" : "=f"(lo), "=f"(hi) : "l"(a)); return make_float2(lo, hi); }

// ------------------------- scratch (device globals) ------------------------
__device__ float g_x[2 * 3 * 256 * 256];
__device__ float g_c1[2 * 32 * 128 * 128];
__device__ float g_c2[2 * 64 * 64 * 64];
__device__ float g_c3[2 * 128 * 32 * 32];
__device__ float g_c4[2 * 256 * 16 * 16];
__device__ float g_feat[2 * 480 * 8 * 8];
__device__ float g_h1[2 * 128 * 8 * 8];
__device__ float g_wT[4320 * 128];
__device__ float g_lpart[30 * 2 * 128 * 8 * 8];
__device__ float g_cpart[2097152];
__device__ float g_wrep[387936];
__device__ float g_G[2 * 3 * 8 * 8 * 256 * 2];   // fused weight*LUT table (G0, dG)

#define WR1_OFF 0
#define WR2_OFF 864
#define WR3_OFF 19296
#define WR4_OFF 93024

// ---------------- prep: all conv weight repacks + lin1 transpose -----------
__global__ void prep_kernel(const float* __restrict__ w1, const float* __restrict__ w2,
                            const float* __restrict__ w3, const float* __restrict__ w4,
                            const float* __restrict__ lw, float* __restrict__ wrep,
                            float* __restrict__ wT) {
    int idx = blockIdx.x * 256 + threadIdx.x;
    if (idx < 864) {
        int oc = idx % 32, p = (idx / 32) % 9, ic = idx / 288;
        wrep[WR1_OFF + idx] = w1[(oc * 3 + ic) * 9 + p];
    } else if (idx < 864 + 18432) {
        int j = idx - 864;
        int oc = j % 64, p = (j / 64) % 9, ic = j / 576;
        wrep[WR2_OFF + j] = w2[(oc * 32 + ic) * 9 + p];
    } else if (idx < 19296 + 73728) {
        int j = idx - 19296;
        int oc = j % 128, p = (j / 128) % 9, ic = j / 1152;
        wrep[WR3_OFF + j] = w3[(oc * 64 + ic) * 9 + p];
    } else if (idx < 93024 + 294912) {
        int j = idx - 93024;
        int oc = j % 256, p = (j / 256) % 9, ic = j / 2304;
        wrep[WR4_OFF + j] = w4[(oc * 128 + ic) * 9 + p];
    } else if (idx < 387936 + 552960) {
        int j = idx - 387936;
        int k = j >> 7, oc = j & 127;
        wT[j] = lw[(long)oc * 4320 + k];
    }
}

// ------------------------------ resize 1024->256 ---------------------------
__global__ void resize256_kernel(const float* __restrict__ img, float* __restrict__ out) {
    int idx = blockIdx.x * blockDim.x + threadIdx.x;
    if (idx >= 2 * 3 * 256 * 256) return;
    int ox = idx & 255;
    int oy = (idx >> 8) & 255;
    int bc = idx >> 16;
    const float scale = 1023.0f / 255.0f;
    float py = oy * scale;
    int iy = (int)py; if (iy > 1022) iy = 1022;
    float fy = py - (float)iy;
    float px = ox * scale;
    int ix = (int)px; if (ix > 1022) ix = 1022;
    float fx = px - (float)ix;
    const float* p = img + ((long)bc << 20) + iy * 1024 + ix;
    float v00 = p[0], v01 = p[1], v10 = p[1024], v11 = p[1025];
    float c0 = v00 + fy * (v10 - v00);
    float c1 = v01 + fy * (v11 - v01);
    out[idx] = c0 + fx * (c1 - c0);
}

// --- stride-2 3x3 conv: 8oc x 4ow, L1 prefetch of next-ic weights+inputs -----
template <int ICC, int OC, int H, bool FUSE>
__global__ __launch_bounds__(256, 2) void conv_v7(
    const float* __restrict__ in, const float* __restrict__ wrep,
    const float* __restrict__ bias, float* __restrict__ out, int ICtot) {
    constexpr int OH = H / 2;
    constexpr int OW = H / 2;
    constexpr int QW = OW / 4;
    constexpr int NOCG = OC / 8;
    constexpr int TOTAL = 2 * NOCG * OH * QW;
    constexpr int NOUT = 2 * OC * OH * OW;
    constexpr int WLINES = (9 * OC * 4 + 127) / 128;   // 128B lines per ic weight slice
    int idx = blockIdx.x * 256 + threadIdx.x;
    if (idx >= TOTAL) return;
    int lane = threadIdx.x & 31;
    int ks = blockIdx.y;
    int ic0 = ks * ICC;

    // ocg fastest within warp (input addresses shared by 8 lanes)
    int ocg = idx % NOCG;
    int q = (idx / NOCG) % QW;
    int oh = (idx / (NOCG * QW)) % OH;
    int b = idx / (NOCG * QW * OH);
    int ow0 = q * 4;
    int oc0 = ocg * 8;
    int base = 2 * ow0;
    int cbeg = base ? base - 2 : 0;

    int rr[3];
#pragma unroll
    for (int kh = 0; kh < 3; kh++) { int r = 2 * oh - 1 + kh; rr[kh] = (r < 0) ? -r : r; }

    ull acc[4][4];
#pragma unroll
    for (int o2 = 0; o2 < 4; o2++) {
        ull bv = (ks == 0) ? pkpair(bias[oc0 + 2 * o2], bias[oc0 + 2 * o2 + 1]) : 0ull;
#pragma unroll
        for (int j = 0; j < 4; j++) acc[o2][j] = bv;
    }

    const float* wslice = wrep + (long)ic0 * 9 * OC;       // block's weight slice
    const float* ipbase = in + (long)(b * ICtot + ic0) * H * H;

    // ---- prologue prefetch: ic=0 weights + input rows ----
    for (int p = lane; p < WLINES; p += 32) pf_l1(wslice + p * 32);
    if (lane < 6) {
        int kh = lane >> 1;
        pf_l1(ipbase + rr[kh] * H + cbeg + (lane & 1) * 32);
    }

    for (int ic = 0; ic < ICC; ic++) {
        const float* ip = ipbase + (long)ic * H * H;
        const float* wp = wslice + ic * 9 * OC + oc0;

        // ---- prefetch next ic's weights + inputs (non-faulting) ----
        if (ic + 1 < ICC) {
            const float* wn = wslice + (ic + 1) * 9 * OC;
            for (int p = lane; p < WLINES; p += 32) pf_l1(wn + p * 32);
            if (lane < 6) {
                int kh = lane >> 1;
                pf_l1(ip + H * H + rr[kh] * H + cbeg + (lane & 1) * 32);
            }
        }

        // ---- batched load phase: all 3 rows, 15 independent LDG.64 ----
        float v[3][10];
        if (base) {
#pragma unroll
            for (int kh = 0; kh < 3; kh++) {
                const float2* r2 = (const float2*)(ip + rr[kh] * H + base - 2);
#pragma unroll
                for (int t = 0; t < 5; t++) {
                    float2 d = __ldg(r2 + t);
                    v[kh][2 * t] = d.x; v[kh][2 * t + 1] = d.y;
                }
            }
        } else {
#pragma unroll
            for (int kh = 0; kh < 3; kh++) {
                const float2* r2 = (const float2*)(ip + rr[kh] * H);
#pragma unroll
                for (int t = 0; t < 4; t++) {
                    float2 d = __ldg(r2 + t);
                    v[kh][2 + 2 * t] = d.x; v[kh][3 + 2 * t] = d.y;
                }
            }
#pragma unroll
            for (int kh = 0; kh < 3; kh++) { v[kh][1] = v[kh][3]; v[kh][0] = 0.f; }
        }

        // ---- compute phase ----
#pragma unroll
        for (int kh = 0; kh < 3; kh++) {
            ull xx[9];
#pragma unroll
            for (int i = 0; i < 9; i++) xx[i] = pk2(v[kh][i + 1]);
#pragma unroll
            for (int kw = 0; kw < 3; kw++) {
                const ulonglong2* w2p = (const ulonglong2*)(wp + (kh * 3 + kw) * OC);
                ulonglong2 wa = __ldg(w2p);
                ulonglong2 wb = __ldg(w2p + 1);
                ull wv[4] = {wa.x, wa.y, wb.x, wb.y};
#pragma unroll
                for (int o2 = 0; o2 < 4; o2++)
#pragma unroll
                    for (int j = 0; j < 4; j++)
                        acc[o2][j] = f2fma(wv[o2], xx[2 * j + kw], acc[o2][j]);
            }
        }
    }

    float* ob = out + (FUSE ? 0l : (long)ks * NOUT);
#pragma unroll
    for (int o2 = 0; o2 < 4; o2++) {
        float2 p0 = upk(acc[o2][0]), p1 = upk(acc[o2][1]), p2 = upk(acc[o2][2]), p3 = upk(acc[o2][3]);
        float ev0 = p0.x, ev1 = p1.x, ev2 = p2.x, ev3 = p3.x;
        float od0 = p0.y, od1 = p1.y, od2 = p2.y, od3 = p3.y;
        if (FUSE) {
            ev0 = silu_f(ev0); ev1 = silu_f(ev1); ev2 = silu_f(ev2); ev3 = silu_f(ev3);
            od0 = silu_f(od0); od1 = silu_f(od1); od2 = silu_f(od2); od3 = silu_f(od3);
        }
        long oe = ((long)(b * OC + oc0 + 2 * o2) * OH + oh) * OW + ow0;
        *(float4*)(ob + oe) = make_float4(ev0, ev1, ev2, ev3);
        *(float4*)(ob + oe + (long)OH * OW) = make_float4(od0, od1, od2, od3);
    }
}

// -------------- split-K reduce + SiLU epilogue (float4 streams) -------------
__global__ void reduce_silu4_kernel(const float4* __restrict__ part, float4* __restrict__ out,
                                    int n4, int ks) {
    int idx = blockIdx.x * blockDim.x + threadIdx.x;
    if (idx >= n4) return;
    float4 s = part[idx];
    for (int k = 1; k < ks; k++) {
        float4 p = part[k * n4 + idx];
        s.x += p.x; s.y += p.y; s.z += p.z; s.w += p.w;
    }
    s.x = silu_f(s.x); s.y = silu_f(s.y); s.z = silu_f(s.z); s.w = silu_f(s.w);
    out[idx] = s;
}

// ----------------------- merged avg pools (warp/output) ---------------------
__global__ void pool_all_kernel(const float* __restrict__ c1, const float* __restrict__ c2,
                                const float* __restrict__ c3, const float* __restrict__ c4,
                                float* __restrict__ feat) {
    int gw = (blockIdx.x * blockDim.x + threadIdx.x) >> 5;
    int lane = threadIdx.x & 31;
    if (gw >= 2 * 480 * 64) return;
    int x = gw & 7;
    int y = (gw >> 3) & 7;
    int cg = (gw >> 6) % 480;
    int b = gw / (480 * 64);
    const float* src; int C, H, k, c;
    if (cg < 32)       { src = c1; C = 32;  H = 128; k = 16; c = cg; }
    else if (cg < 96)  { src = c2; C = 64;  H = 64;  k = 8;  c = cg - 32; }
    else if (cg < 224) { src = c3; C = 128; H = 32;  k = 4;  c = cg - 96; }
    else               { src = c4; C = 256; H = 16;  k = 2;  c = cg - 224; }
    const float* base = src + ((long)(b * C + c) * H + y * k) * H + x * k;
    float s = 0.f;
    int kk = k * k;
    for (int i = lane; i < kk; i += 32) s += base[(i / k) * H + (i % k)];
#pragma unroll
    for (int off = 16; off > 0; off >>= 1) s += __shfl_down_sync(0xffffffffu, s, off);
    if (lane == 0) feat[((b * 480 + cg) * 8 + y) * 8 + x] = s * (1.f / (float)kk);
}

// ----------------- lin1: 3x3 reflect conv 480->128 on 8x8 -------------------
__global__ __launch_bounds__(128) void lin1_kernel(const float* __restrict__ feat,
                                                   const float* __restrict__ wT,
                                                   float* __restrict__ part) {
    __shared__ float slab[16 * 3 * 8];
    int kc = blockIdx.x;
    int oh = blockIdx.y;
    int b = blockIdx.z;
    int t = threadIdx.x;
    int ic0 = kc * 16;

    int ihs[3];
#pragma unroll
    for (int kh = 0; kh < 3; kh++) {
        int r = oh - 1 + kh;
        if (r < 0) r = -r;
        if (r > 7) r = 14 - r;
        ihs[kh] = r;
    }
    for (int j = t; j < 384; j += 128) {
        int icl = j / 24;
        int rem = j % 24;
        int r = rem / 8, col = rem % 8;
        slab[j] = feat[((b * 480 + ic0 + icl) * 8 + ihs[r]) * 8 + col];
    }
    __syncthreads();

    float acc[8];
#pragma unroll
    for (int ow = 0; ow < 8; ow++) acc[ow] = 0.f;

    const int IWT[10] = {1, 0, 1, 2, 3, 4, 5, 6, 7, 6};
#pragma unroll 2
    for (int icl = 0; icl < 16; icl++) {
        float rv[3][8];
#pragma unroll
        for (int r = 0; r < 3; r++)
#pragma unroll
            for (int col = 0; col < 8; col++) rv[r][col] = slab[icl * 24 + r * 8 + col];
#pragma unroll
        for (int kh = 0; kh < 3; kh++)
#pragma unroll
            for (int kw = 0; kw < 3; kw++) {
                float wv = __ldg(wT + (long)((ic0 + icl) * 9 + kh * 3 + kw) * 128 + t);
#pragma unroll
                for (int ow = 0; ow < 8; ow++) acc[ow] += wv * rv[kh][IWT[ow + kw]];
            }
    }
    int base = (((kc * 2 + b) * 128 + t) * 8 + oh) * 8;
#pragma unroll
    for (int ow = 0; ow < 8; ow++) part[base + ow] = acc[ow];
}

__global__ void lin1_reduce_kernel(const float* __restrict__ part,
                                   const float* __restrict__ bias, float* __restrict__ h1) {
    int idx = blockIdx.x * blockDim.x + threadIdx.x;
    if (idx >= 16384) return;
    int oc = (idx >> 6) & 127;
    float s = bias[oc];
#pragma unroll 6
    for (int kc = 0; kc < 30; kc++) s += part[kc * 16384 + idx];
    h1[idx] = silu_f(s);
}

// ---- fused lin2 (1x1 conv 128->27 + sigmoid) + G table build ---------------
__global__ __launch_bounds__(256) void gprep2_kernel(
    const float* __restrict__ h1, const float* __restrict__ w2,
    const float* __restrict__ b2, const float* __restrict__ luts,
    float* __restrict__ G) {
    int gy = blockIdx.x & 7;
    int c = (blockIdx.x >> 3) % 3;
    int b = blockIdx.x / 24;
    __shared__ float sh1[128][8];
    __shared__ float wk[9][8];
    int tid = threadIdx.x;
    for (int j = tid; j < 1024; j += 256) {
        int ic = j >> 3, gx = j & 7;
        sh1[ic][gx] = h1[(b * 128 + ic) * 64 + gy * 8 + gx];
    }
    __syncthreads();
    if (tid < 72) {
        int k = tid >> 3, gx = tid & 7;
        float acc = b2[c * 9 + k];
        const float* wp = w2 + (c * 9 + k) * 128;
#pragma unroll 8
        for (int ic = 0; ic < 128; ic++) acc = fmaf(__ldg(wp + ic), sh1[ic][gx], acc);
        wk[k][gx] = sigm_f(acc);
    }
    __syncthreads();
    for (int j = tid; j < 2048; j += 256) {
        int gx = j >> 8;
        int i = j & 255;
        float g0 = 0.f, g1 = 0.f;
#pragma unroll
        for (int k = 0; k < 9; k++) {
            const float* lp = luts + (c * 9 + k) * 256;
            float l0 = lp[i];
            float l1 = (i < 255) ? lp[i + 1] : l0;
            g0 = fmaf(wk[k][gx], l0, g0);
            g1 = fmaf(wk[k][gx], l1, g1);
        }
        long o = ((((long)(b * 3 + c) * 8 + gy) * 8 + gx) * 256 + i) * 2;
        G[o] = g0;
        G[o + 1] = g1 - g0;
    }
}

// --------- final: per-pixel 4-corner gather from fused G table --------------
__global__ __launch_bounds__(512) void final_v3(const float* __restrict__ img,
                                                const float* __restrict__ G,
                                                float* __restrict__ out) {
    extern __shared__ float sG[];  // 36864 floats = 147456 B
    int rg = blockIdx.x;
    int b = blockIdx.y;
    int tid = threadIdx.x;
    int h0 = rg * 16;
    const float sc = 7.0f / 1023.0f;

    int g0row = (int)(h0 * sc); if (g0row > 6) g0row = 6;
    int gy_base = (g0row > 5) ? 5 : g0row;

    for (int j = tid; j < 9216; j += 512) {
        int cg = j / 1024;
        int r = j % 1024;
        int c = cg / 3, gyl = cg % 3;
        long src = (((long)(b * 3 + c) * 8 + (gy_base + gyl)) * 8) * 512;
        ((float4*)sG)[cg * 1024 + r] = *(const float4*)(G + src + r * 4);
    }
    __syncthreads();

    int w0 = tid * 2;
    int gxp[2]; float fwp[2];
#pragma unroll
    for (int px = 0; px < 2; px++) {
        float pwv = (w0 + px) * sc;
        int gx = (int)pwv; if (gx > 6) gx = 6;
        gxp[px] = gx;
        fwp[px] = pwv - (float)gx;
    }

    const float2* sgp = (const float2*)sG;

    for (int r = 0; r < 16; r++) {
        int h = h0 + r;
        float ph = h * sc;
        int gy0 = (int)ph; if (gy0 > 6) gy0 = 6;
        float fh = ph - (float)gy0;
        int gyl = gy0 - gy_base;

#pragma unroll
        for (int c = 0; c < 3; c++) {
            long ib = ((long)(b * 3 + c) << 20) + ((long)h << 10) + w0;
            float2 iv = *(const float2*)(img + ib);
            float2 res;
            const float2* crow = sgp + (c * 3 + gyl) * 2048;
#pragma unroll
            for (int px = 0; px < 2; px++) {
                float v = px ? iv.y : iv.x;
                float p = fminf(fmaxf(v, 0.f), 1.f) * 255.0f;
                int i0 = (int)p; if (i0 > 254) i0 = 254;
                float fr = p - (float)i0;
                const float2* b00 = crow + gxp[px] * 256;
                float2 A = b00[i0];
                float2 Bv = b00[256 + i0];
                float2 Cv = b00[2048 + i0];
                float2 Dv = b00[2048 + 256 + i0];
                float va = fmaf(fr, A.y, A.x);
                float vb = fmaf(fr, Bv.y, Bv.x);
                float vc = fmaf(fr, Cv.y, Cv.x);
                float vd = fmaf(fr, Dv.y, Dv.x);
                float fw = fwp[px];
                float top = fmaf(fw, vb - va, va);
                float bot = fmaf(fw, vd - vc, vc);
                float rv = fmaf(fh, bot - top, top);
                rv = fminf(fmaxf(rv, 0.f), 1.f);
                if (px) res.y = rv; else res.x = rv;
            }
            *(float2*)(out + ib) = res;
        }
    }
}

// --------------------------------- launch ----------------------------------
extern "C" void kernel_launch(void* const* d_in, const int* in_sizes, int n_in,
                              void* d_out, int out_size) {
    const float* img     = (const float*)d_in[0];
    const float* conv1_w = (const float*)d_in[1];
    const float* conv1_b = (const float*)d_in[2];
    const float* conv2_w = (const float*)d_in[3];
    const float* conv2_b = (const float*)d_in[4];
    const float* conv3_w = (const float*)d_in[5];
    const float* conv3_b = (const float*)d_in[6];
    const float* conv4_w = (const float*)d_in[7];
    const float* conv4_b = (const float*)d_in[8];
    const float* lin1_w  = (const float*)d_in[9];
    const float* lin1_b  = (const float*)d_in[10];
    const float* lin2_w  = (const float*)d_in[11];
    const float* lin2_b  = (const float*)d_in[12];
    const float* luts    = (const float*)d_in[13];
    float* out = (float*)d_out;

    float *px, *pc1, *pc2, *pc3, *pc4, *pfeat, *ph1, *pwT, *plp, *pcp, *pwr, *pG;
    cudaGetSymbolAddress((void**)&px, g_x);
    cudaGetSymbolAddress((void**)&pc1, g_c1);
    cudaGetSymbolAddress((void**)&pc2, g_c2);
    cudaGetSymbolAddress((void**)&pc3, g_c3);
    cudaGetSymbolAddress((void**)&pc4, g_c4);
    cudaGetSymbolAddress((void**)&pfeat, g_feat);
    cudaGetSymbolAddress((void**)&ph1, g_h1);
    cudaGetSymbolAddress((void**)&pwT, g_wT);
    cudaGetSymbolAddress((void**)&plp, g_lpart);
    cudaGetSymbolAddress((void**)&pcp, g_cpart);
    cudaGetSymbolAddress((void**)&pwr, g_wrep);
    cudaGetSymbolAddress((void**)&pG, g_G);

    cudaFuncSetAttribute(final_v3, cudaFuncAttributeMaxDynamicSharedMemorySize, 147456);

    // 0. prep: weight repacks + lin1 transpose
    prep_kernel<<<3676, 256>>>(conv1_w, conv2_w, conv3_w, conv4_w, lin1_w, pwr, pwT);

    // 1. resize 1024 -> 256
    resize256_kernel<<<1536, 256>>>(img, px);

    // 2-5. conv stack (prefetching conv_v7, split-K)
    conv_v7<3, 32, 256, true><<<dim3(128, 1), 256>>>(px, pwr + WR1_OFF, conv1_b, pc1, 3);

    conv_v7<8, 64, 128, false><<<dim3(64, 4), 256>>>(pc1, pwr + WR2_OFF, conv2_b, pcp, 32);
    reduce_silu4_kernel<<<512, 256>>>((const float4*)pcp, (float4*)pc2, 131072, 4);

    conv_v7<8, 128, 64, false><<<dim3(32, 8), 256>>>(pc2, pwr + WR3_OFF, conv3_b, pcp, 64);
    reduce_silu4_kernel<<<256, 256>>>((const float4*)pcp, (float4*)pc3, 65536, 8);

    conv_v7<8, 256, 32, false><<<dim3(16, 16), 256>>>(pc3, pwr + WR4_OFF, conv4_b, pcp, 128);
    reduce_silu4_kernel<<<128, 256>>>((const float4*)pcp, (float4*)pc4, 32768, 16);

    // 6. merged multi-scale avg pools
    pool_all_kernel<<<7680, 256>>>(pc1, pc2, pc3, pc4, pfeat);

    // 7. lin1 (480->128, 3x3 reflect, SiLU), split-K x30
    lin1_kernel<<<dim3(30, 8, 2), 128>>>(pfeat, pwT, plp);
    lin1_reduce_kernel<<<64, 256>>>(plp, lin1_b, ph1);

    // 8+9. fused lin2 + G table
    gprep2_kernel<<<48, 256>>>(ph1, lin2_w, lin2_b, luts, pG);

    // 10. final: 4-corner gather + clip
    final_v3<<<dim3(64, 2), 512, 147456>>>(img, pG, out);
}

// round 12
// speedup vs baseline: 1.0454x; 1.0454x over previous
#include <cuda_runtime.h>
#include <math.h>

#define DINL __device__ __forceinline__
typedef unsigned long long ull;

DINL float silu_f(float x) { return x / (1.f + expf(-x)); }
DINL float sigm_f(float x) { return 1.f / (1.f + expf(-x)); }

// ---------------- packed f32x2 helpers (sm_100+) ----------------
DINL ull pk2(float x) { ull r; asm("mov.b64 %0,{%1,%1};" : "=l"(r) : "f"(x)); return r; }
DINL ull pkpair(float a, float b) { ull r; asm("mov.b64 %0,{%1,%2};" : "=l"(r) : "f"(a), "f"(b)); return r; }
DINL ull f2fma(ull a, ull b, ull c) {
    ull d; asm("fma.rn.f32x2 %0,%1,%2,%3;" : "=l"(d) : "l"(a), "l"(b), "l"(c)); return d;
}
DINL float2 upk(ull a) { float lo, hi; asm("mov.b64 {%0,%1},%2;" : "=f"(lo), "=f"(hi) : "l"(a)); return make_float2(lo, hi); }

// ------------------------- scratch (device globals) ------------------------
__device__ float g_x[2 * 3 * 256 * 256];
__device__ float g_c1[2 * 32 * 128 * 128];
__device__ float g_c2[2 * 64 * 64 * 64];
__device__ float g_c3[2 * 128 * 32 * 32];
__device__ float g_c4[2 * 256 * 16 * 16];
__device__ float g_feat[2 * 480 * 8 * 8];
__device__ float g_h1[2 * 128 * 8 * 8];
__device__ float g_wT[4320 * 128];
__device__ float g_lpart[30 * 2 * 128 * 8 * 8];
__device__ float g_cpart[2097152];
__device__ float g_wrep[387936];
__device__ float g_G[2 * 3 * 8 * 8 * 256 * 2];   // fused weight*LUT table (G0, dG)

#define WR1_OFF 0
#define WR2_OFF 864
#define WR3_OFF 19296
#define WR4_OFF 93024

// ------ merged prep: resize 1024->256 (blocks 0..1535) + weight repacks -----
__global__ void prep_resize_kernel(const float* __restrict__ img, float* __restrict__ xout,
                                   const float* __restrict__ w1, const float* __restrict__ w2,
                                   const float* __restrict__ w3, const float* __restrict__ w4,
                                   const float* __restrict__ lw, float* __restrict__ wrep,
                                   float* __restrict__ wT) {
    if (blockIdx.x < 1536) {
        int idx = blockIdx.x * 256 + threadIdx.x;
        int ox = idx & 255;
        int oy = (idx >> 8) & 255;
        int bc = idx >> 16;
        const float scale = 1023.0f / 255.0f;
        float py = oy * scale;
        int iy = (int)py; if (iy > 1022) iy = 1022;
        float fy = py - (float)iy;
        float px = ox * scale;
        int ix = (int)px; if (ix > 1022) ix = 1022;
        float fx = px - (float)ix;
        const float* p = img + ((long)bc << 20) + iy * 1024 + ix;
        float v00 = p[0], v01 = p[1], v10 = p[1024], v11 = p[1025];
        float c0 = v00 + fy * (v10 - v00);
        float c1 = v01 + fy * (v11 - v01);
        xout[idx] = c0 + fx * (c1 - c0);
        return;
    }
    int idx = (blockIdx.x - 1536) * 256 + threadIdx.x;
    if (idx < 864) {
        int oc = idx % 32, p = (idx / 32) % 9, ic = idx / 288;
        wrep[WR1_OFF + idx] = w1[(oc * 3 + ic) * 9 + p];
    } else if (idx < 864 + 18432) {
        int j = idx - 864;
        int oc = j % 64, p = (j / 64) % 9, ic = j / 576;
        wrep[WR2_OFF + j] = w2[(oc * 32 + ic) * 9 + p];
    } else if (idx < 19296 + 73728) {
        int j = idx - 19296;
        int oc = j % 128, p = (j / 128) % 9, ic = j / 1152;
        wrep[WR3_OFF + j] = w3[(oc * 64 + ic) * 9 + p];
    } else if (idx < 93024 + 294912) {
        int j = idx - 93024;
        int oc = j % 256, p = (j / 256) % 9, ic = j / 2304;
        wrep[WR4_OFF + j] = w4[(oc * 128 + ic) * 9 + p];
    } else if (idx < 387936 + 552960) {
        int j = idx - 387936;
        int k = j >> 7, oc = j & 127;
        wT[j] = lw[(long)oc * 4320 + k];
    }
}

// --- stride-2 3x3 conv: 8oc x 4ow, wide input loads (.64+.128+.128), split-K -
template <int ICC, int OC, int H, bool FUSE>
__global__ __launch_bounds__(256, 2) void conv_v8(
    const float* __restrict__ in, const float* __restrict__ wrep,
    const float* __restrict__ bias, float* __restrict__ out, int ICtot) {
    constexpr int OH = H / 2;
    constexpr int OW = H / 2;
    constexpr int QW = OW / 4;
    constexpr int NOCG = OC / 8;
    constexpr int TOTAL = 2 * NOCG * OH * QW;
    constexpr int NOUT = 2 * OC * OH * OW;
    int idx = blockIdx.x * blockDim.x + threadIdx.x;
    if (idx >= TOTAL) return;
    int ks = blockIdx.y;
    int ic0 = ks * ICC;

    // ocg fastest within warp (input addresses broadcast across 8 lanes)
    int ocg = idx % NOCG;
    int q = (idx / NOCG) % QW;
    int oh = (idx / (NOCG * QW)) % OH;
    int b = idx / (NOCG * QW * OH);
    int ow0 = q * 4;
    int oc0 = ocg * 8;
    int base = 2 * ow0;

    int rr[3];
#pragma unroll
    for (int kh = 0; kh < 3; kh++) { int r = 2 * oh - 1 + kh; rr[kh] = (r < 0) ? -r : r; }

    ull acc[4][4];
#pragma unroll
    for (int o2 = 0; o2 < 4; o2++) {
        ull bv = (ks == 0) ? pkpair(bias[oc0 + 2 * o2], bias[oc0 + 2 * o2 + 1]) : 0ull;
#pragma unroll
        for (int j = 0; j < 4; j++) acc[o2][j] = bv;
    }

    const float* wbase = wrep + (long)ic0 * 9 * OC + oc0;

    for (int ic = 0; ic < ICC; ic++) {
        const float* ip = in + (long)(b * ICtot + ic0 + ic) * H * H;
        const float* wp = wbase + (long)ic * 9 * OC;

        // ---- batched wide-load phase: 3 rows x (.64 + .128 + .128) ----
        float v[3][10];
        if (base) {
#pragma unroll
            for (int kh = 0; kh < 3; kh++) {
                const float* rp = ip + rr[kh] * H + base;
                float2 a = __ldg((const float2*)(rp - 2));
                float4 m = __ldg((const float4*)rp);
                float4 e = __ldg((const float4*)(rp + 4));
                v[kh][0] = a.x; v[kh][1] = a.y;
                v[kh][2] = m.x; v[kh][3] = m.y; v[kh][4] = m.z; v[kh][5] = m.w;
                v[kh][6] = e.x; v[kh][7] = e.y; v[kh][8] = e.z; v[kh][9] = e.w;
            }
        } else {
#pragma unroll
            for (int kh = 0; kh < 3; kh++) {
                const float* rp = ip + rr[kh] * H;
                float4 m = __ldg((const float4*)rp);
                float4 e = __ldg((const float4*)(rp + 4));
                v[kh][2] = m.x; v[kh][3] = m.y; v[kh][4] = m.z; v[kh][5] = m.w;
                v[kh][6] = e.x; v[kh][7] = e.y; v[kh][8] = e.z; v[kh][9] = e.w;
                v[kh][1] = m.y;  // reflect: col -1 -> col 1
                v[kh][0] = 0.f;
            }
        }

        // ---- compute phase ----
#pragma unroll
        for (int kh = 0; kh < 3; kh++) {
            ull xx[9];
#pragma unroll
            for (int i = 0; i < 9; i++) xx[i] = pk2(v[kh][i + 1]);
#pragma unroll
            for (int kw = 0; kw < 3; kw++) {
                const ulonglong2* w2p = (const ulonglong2*)(wp + (kh * 3 + kw) * OC);
                ulonglong2 wa = __ldg(w2p);
                ulonglong2 wb = __ldg(w2p + 1);
                ull wv[4] = {wa.x, wa.y, wb.x, wb.y};
#pragma unroll
                for (int o2 = 0; o2 < 4; o2++)
#pragma unroll
                    for (int j = 0; j < 4; j++)
                        acc[o2][j] = f2fma(wv[o2], xx[2 * j + kw], acc[o2][j]);
            }
        }
    }

    float* ob = out + (FUSE ? 0l : (long)ks * NOUT);
#pragma unroll
    for (int o2 = 0; o2 < 4; o2++) {
        float2 p0 = upk(acc[o2][0]), p1 = upk(acc[o2][1]), p2 = upk(acc[o2][2]), p3 = upk(acc[o2][3]);
        float ev0 = p0.x, ev1 = p1.x, ev2 = p2.x, ev3 = p3.x;
        float od0 = p0.y, od1 = p1.y, od2 = p2.y, od3 = p3.y;
        if (FUSE) {
            ev0 = silu_f(ev0); ev1 = silu_f(ev1); ev2 = silu_f(ev2); ev3 = silu_f(ev3);
            od0 = silu_f(od0); od1 = silu_f(od1); od2 = silu_f(od2); od3 = silu_f(od3);
        }
        long oe = ((long)(b * OC + oc0 + 2 * o2) * OH + oh) * OW + ow0;
        *(float4*)(ob + oe) = make_float4(ev0, ev1, ev2, ev3);
        *(float4*)(ob + oe + (long)OH * OW) = make_float4(od0, od1, od2, od3);
    }
}

// -------------- split-K reduce + SiLU epilogue (float4 streams) -------------
__global__ void reduce_silu4_kernel(const float4* __restrict__ part, float4* __restrict__ out,
                                    int n4, int ks) {
    int idx = blockIdx.x * blockDim.x + threadIdx.x;
    if (idx >= n4) return;
    float4 s = part[idx];
    for (int k = 1; k < ks; k++) {
        float4 p = part[k * n4 + idx];
        s.x += p.x; s.y += p.y; s.z += p.z; s.w += p.w;
    }
    s.x = silu_f(s.x); s.y = silu_f(s.y); s.z = silu_f(s.z); s.w = silu_f(s.w);
    out[idx] = s;
}

// ----------------------- merged avg pools (warp/output) ---------------------
__global__ void pool_all_kernel(const float* __restrict__ c1, const float* __restrict__ c2,
                                const float* __restrict__ c3, const float* __restrict__ c4,
                                float* __restrict__ feat) {
    int gw = (blockIdx.x * blockDim.x + threadIdx.x) >> 5;
    int lane = threadIdx.x & 31;
    if (gw >= 2 * 480 * 64) return;
    int x = gw & 7;
    int y = (gw >> 3) & 7;
    int cg = (gw >> 6) % 480;
    int b = gw / (480 * 64);
    const float* src; int C, H, k, c;
    if (cg < 32)       { src = c1; C = 32;  H = 128; k = 16; c = cg; }
    else if (cg < 96)  { src = c2; C = 64;  H = 64;  k = 8;  c = cg - 32; }
    else if (cg < 224) { src = c3; C = 128; H = 32;  k = 4;  c = cg - 96; }
    else               { src = c4; C = 256; H = 16;  k = 2;  c = cg - 224; }
    const float* base = src + ((long)(b * C + c) * H + y * k) * H + x * k;
    float s = 0.f;
    int kk = k * k;
    for (int i = lane; i < kk; i += 32) s += base[(i / k) * H + (i % k)];
#pragma unroll
    for (int off = 16; off > 0; off >>= 1) s += __shfl_down_sync(0xffffffffu, s, off);
    if (lane == 0) feat[((b * 480 + cg) * 8 + y) * 8 + x] = s * (1.f / (float)kk);
}

// ----------------- lin1: 3x3 reflect conv 480->128 on 8x8 -------------------
__global__ __launch_bounds__(128) void lin1_kernel(const float* __restrict__ feat,
                                                   const float* __restrict__ wT,
                                                   float* __restrict__ part) {
    __shared__ float slab[16 * 3 * 8];
    int kc = blockIdx.x;
    int oh = blockIdx.y;
    int b = blockIdx.z;
    int t = threadIdx.x;
    int ic0 = kc * 16;

    int ihs[3];
#pragma unroll
    for (int kh = 0; kh < 3; kh++) {
        int r = oh - 1 + kh;
        if (r < 0) r = -r;
        if (r > 7) r = 14 - r;
        ihs[kh] = r;
    }
    for (int j = t; j < 384; j += 128) {
        int icl = j / 24;
        int rem = j % 24;
        int r = rem / 8, col = rem % 8;
        slab[j] = feat[((b * 480 + ic0 + icl) * 8 + ihs[r]) * 8 + col];
    }
    __syncthreads();

    float acc[8];
#pragma unroll
    for (int ow = 0; ow < 8; ow++) acc[ow] = 0.f;

    const int IWT[10] = {1, 0, 1, 2, 3, 4, 5, 6, 7, 6};
#pragma unroll 2
    for (int icl = 0; icl < 16; icl++) {
        float rv[3][8];
#pragma unroll
        for (int r = 0; r < 3; r++)
#pragma unroll
            for (int col = 0; col < 8; col++) rv[r][col] = slab[icl * 24 + r * 8 + col];
#pragma unroll
        for (int kh = 0; kh < 3; kh++)
#pragma unroll
            for (int kw = 0; kw < 3; kw++) {
                float wv = __ldg(wT + (long)((ic0 + icl) * 9 + kh * 3 + kw) * 128 + t);
#pragma unroll
                for (int ow = 0; ow < 8; ow++) acc[ow] += wv * rv[kh][IWT[ow + kw]];
            }
    }
    int base = (((kc * 2 + b) * 128 + t) * 8 + oh) * 8;
#pragma unroll
    for (int ow = 0; ow < 8; ow++) part[base + ow] = acc[ow];
}

__global__ void lin1_reduce_kernel(const float* __restrict__ part,
                                   const float* __restrict__ bias, float* __restrict__ h1) {
    int idx = blockIdx.x * blockDim.x + threadIdx.x;
    if (idx >= 16384) return;
    int oc = (idx >> 6) & 127;
    float s = bias[oc];
#pragma unroll 6
    for (int kc = 0; kc < 30; kc++) s += part[kc * 16384 + idx];
    h1[idx] = silu_f(s);
}

// ---- fused lin2 (1x1 conv 128->27 + sigmoid) + G table build ---------------
__global__ __launch_bounds__(256) void gprep2_kernel(
    const float* __restrict__ h1, const float* __restrict__ w2,
    const float* __restrict__ b2, const float* __restrict__ luts,
    float* __restrict__ G) {
    int gy = blockIdx.x & 7;
    int c = (blockIdx.x >> 3) % 3;
    int b = blockIdx.x / 24;
    __shared__ float sh1[128][8];
    __shared__ float wk[9][8];
    int tid = threadIdx.x;
    for (int j = tid; j < 1024; j += 256) {
        int ic = j >> 3, gx = j & 7;
        sh1[ic][gx] = h1[(b * 128 + ic) * 64 + gy * 8 + gx];
    }
    __syncthreads();
    if (tid < 72) {
        int k = tid >> 3, gx = tid & 7;
        float acc = b2[c * 9 + k];
        const float* wp = w2 + (c * 9 + k) * 128;
#pragma unroll 8
        for (int ic = 0; ic < 128; ic++) acc = fmaf(__ldg(wp + ic), sh1[ic][gx], acc);
        wk[k][gx] = sigm_f(acc);
    }
    __syncthreads();
    for (int j = tid; j < 2048; j += 256) {
        int gx = j >> 8;
        int i = j & 255;
        float g0 = 0.f, g1 = 0.f;
#pragma unroll
        for (int k = 0; k < 9; k++) {
            const float* lp = luts + (c * 9 + k) * 256;
            float l0 = lp[i];
            float l1 = (i < 255) ? lp[i + 1] : l0;
            g0 = fmaf(wk[k][gx], l0, g0);
            g1 = fmaf(wk[k][gx], l1, g1);
        }
        long o = ((((long)(b * 3 + c) * 8 + gy) * 8 + gx) * 256 + i) * 2;
        G[o] = g0;
        G[o + 1] = g1 - g0;
    }
}

// --------- final: per-pixel 4-corner gather from fused G table --------------
__global__ __launch_bounds__(512) void final_v3(const float* __restrict__ img,
                                                const float* __restrict__ G,
                                                float* __restrict__ out) {
    extern __shared__ float sG[];  // 36864 floats = 147456 B
    int rg = blockIdx.x;
    int b = blockIdx.y;
    int tid = threadIdx.x;
    int h0 = rg * 16;
    const float sc = 7.0f / 1023.0f;

    int g0row = (int)(h0 * sc); if (g0row > 6) g0row = 6;
    int gy_base = (g0row > 5) ? 5 : g0row;

    for (int j = tid; j < 9216; j += 512) {
        int cg = j / 1024;
        int r = j % 1024;
        int c = cg / 3, gyl = cg % 3;
        long src = (((long)(b * 3 + c) * 8 + (gy_base + gyl)) * 8) * 512;
        ((float4*)sG)[cg * 1024 + r] = *(const float4*)(G + src + r * 4);
    }
    __syncthreads();

    int w0 = tid * 2;
    int gxp[2]; float fwp[2];
#pragma unroll
    for (int px = 0; px < 2; px++) {
        float pwv = (w0 + px) * sc;
        int gx = (int)pwv; if (gx > 6) gx = 6;
        gxp[px] = gx;
        fwp[px] = pwv - (float)gx;
    }

    const float2* sgp = (const float2*)sG;

    for (int r = 0; r < 16; r++) {
        int h = h0 + r;
        float ph = h * sc;
        int gy0 = (int)ph; if (gy0 > 6) gy0 = 6;
        float fh = ph - (float)gy0;
        int gyl = gy0 - gy_base;

#pragma unroll
        for (int c = 0; c < 3; c++) {
            long ib = ((long)(b * 3 + c) << 20) + ((long)h << 10) + w0;
            float2 iv = *(const float2*)(img + ib);
            float2 res;
            const float2* crow = sgp + (c * 3 + gyl) * 2048;
#pragma unroll
            for (int px = 0; px < 2; px++) {
                float v = px ? iv.y : iv.x;
                float p = fminf(fmaxf(v, 0.f), 1.f) * 255.0f;
                int i0 = (int)p; if (i0 > 254) i0 = 254;
                float fr = p - (float)i0;
                const float2* b00 = crow + gxp[px] * 256;
                float2 A = b00[i0];
                float2 Bv = b00[256 + i0];
                float2 Cv = b00[2048 + i0];
                float2 Dv = b00[2048 + 256 + i0];
                float va = fmaf(fr, A.y, A.x);
                float vb = fmaf(fr, Bv.y, Bv.x);
                float vc = fmaf(fr, Cv.y, Cv.x);
                float vd = fmaf(fr, Dv.y, Dv.x);
                float fw = fwp[px];
                float top = fmaf(fw, vb - va, va);
                float bot = fmaf(fw, vd - vc, vc);
                float rv = fmaf(fh, bot - top, top);
                rv = fminf(fmaxf(rv, 0.f), 1.f);
                if (px) res.y = rv; else res.x = rv;
            }
            *(float2*)(out + ib) = res;
        }
    }
}

// --------------------------------- launch ----------------------------------
extern "C" void kernel_launch(void* const* d_in, const int* in_sizes, int n_in,
                              void* d_out, int out_size) {
    const float* img     = (const float*)d_in[0];
    const float* conv1_w = (const float*)d_in[1];
    const float* conv1_b = (const float*)d_in[2];
    const float* conv2_w = (const float*)d_in[3];
    const float* conv2_b = (const float*)d_in[4];
    const float* conv3_w = (const float*)d_in[5];
    const float* conv3_b = (const float*)d_in[6];
    const float* conv4_w = (const float*)d_in[7];
    const float* conv4_b = (const float*)d_in[8];
    const float* lin1_w  = (const float*)d_in[9];
    const float* lin1_b  = (const float*)d_in[10];
    const float* lin2_w  = (const float*)d_in[11];
    const float* lin2_b  = (const float*)d_in[12];
    const float* luts    = (const float*)d_in[13];
    float* out = (float*)d_out;

    float *px, *pc1, *pc2, *pc3, *pc4, *pfeat, *ph1, *pwT, *plp, *pcp, *pwr, *pG;
    cudaGetSymbolAddress((void**)&px, g_x);
    cudaGetSymbolAddress((void**)&pc1, g_c1);
    cudaGetSymbolAddress((void**)&pc2, g_c2);
    cudaGetSymbolAddress((void**)&pc3, g_c3);
    cudaGetSymbolAddress((void**)&pc4, g_c4);
    cudaGetSymbolAddress((void**)&pfeat, g_feat);
    cudaGetSymbolAddress((void**)&ph1, g_h1);
    cudaGetSymbolAddress((void**)&pwT, g_wT);
    cudaGetSymbolAddress((void**)&plp, g_lpart);
    cudaGetSymbolAddress((void**)&pcp, g_cpart);
    cudaGetSymbolAddress((void**)&pwr, g_wrep);
    cudaGetSymbolAddress((void**)&pG, g_G);

    cudaFuncSetAttribute(final_v3, cudaFuncAttributeMaxDynamicSharedMemorySize, 147456);

    // 0. merged prep (weight repacks + lin1 transpose) + resize 1024->256
    prep_resize_kernel<<<1536 + 3676, 256>>>(img, px, conv1_w, conv2_w, conv3_w,
                                             conv4_w, lin1_w, pwr, pwT);

    // 2-5. conv stack (wide-load conv_v8, split-K)
    // conv1: 128-thread blocks -> 256 blocks for full-chip coverage
    conv_v8<3, 32, 256, true><<<dim3(256, 1), 128>>>(px, pwr + WR1_OFF, conv1_b, pc1, 3);

    conv_v8<8, 64, 128, false><<<dim3(64, 4), 256>>>(pc1, pwr + WR2_OFF, conv2_b, pcp, 32);
    reduce_silu4_kernel<<<512, 256>>>((const float4*)pcp, (float4*)pc2, 131072, 4);

    conv_v8<8, 128, 64, false><<<dim3(32, 8), 256>>>(pc2, pwr + WR3_OFF, conv3_b, pcp, 64);
    reduce_silu4_kernel<<<256, 256>>>((const float4*)pcp, (float4*)pc3, 65536, 8);

    conv_v8<8, 256, 32, false><<<dim3(16, 16), 256>>>(pc3, pwr + WR4_OFF, conv4_b, pcp, 128);
    reduce_silu4_kernel<<<128, 256>>>((const float4*)pcp, (float4*)pc4, 32768, 16);

    // 6. merged multi-scale avg pools
    pool_all_kernel<<<7680, 256>>>(pc1, pc2, pc3, pc4, pfeat);

    // 7. lin1 (480->128, 3x3 reflect, SiLU), split-K x30
    lin1_kernel<<<dim3(30, 8, 2), 128>>>(pfeat, pwT, plp);
    lin1_reduce_kernel<<<64, 256>>>(plp, lin1_b, ph1);

    // 8+9. fused lin2 + G table
    gprep2_kernel<<<48, 256>>>(ph1, lin2_w, lin2_b, luts, pG);

    // 10. final: 4-corner gather + clip
    final_v3<<<dim3(64, 2), 512, 147456>>>(img, pG, out);
}

// round 13
// speedup vs baseline: 1.1771x; 1.1260x over previous
#include <cuda_runtime.h>
#include <math.h>

#define DINL __device__ __forceinline__
typedef unsigned long long ull;

DINL float silu_f(float x) { return x / (1.f + expf(-x)); }
DINL float sigm_f(float x) { return 1.f / (1.f + expf(-x)); }

// ---------------- packed f32x2 helpers (sm_100+) ----------------
DINL ull pk2(float x) { ull r; asm("mov.b64 %0,{%1,%1};" : "=l"(r) : "f"(x)); return r; }
DINL ull pkpair(float a, float b) { ull r; asm("mov.b64 %0,{%1,%2};" : "=l"(r) : "f"(a), "f"(b)); return r; }
DINL ull f2fma(ull a, ull b, ull c) {
    ull d; asm("fma.rn.f32x2 %0,%1,%2,%3;" : "=l"(d) : "l"(a), "l"(b), "l"(c)); return d;
}
DINL float2 upk(ull a) { float lo, hi; asm("mov.b64 {%0,%1},%2;" : "=f"(lo), "=f"(hi) : "l"(a)); return make_float2(lo, hi); }

// ------------------------- scratch (device globals) ------------------------
__device__ float g_x[2 * 3 * 256 * 256];
__device__ float g_c1[2 * 32 * 128 * 128];
__device__ float g_c2[2 * 64 * 64 * 64];
__device__ float g_c3[2 * 128 * 32 * 32];
__device__ float g_c4[2 * 256 * 16 * 16];
__device__ float g_feat[2 * 480 * 8 * 8];
__device__ float g_h1[2 * 128 * 8 * 8];
__device__ float g_wT[4320 * 128];
__device__ float g_lpart[30 * 2 * 128 * 8 * 8];
__device__ float g_cpart[2097152];
__device__ float g_wrep[387936];
__device__ float g_G[2 * 3 * 8 * 8 * 256 * 2];   // fused weight*LUT table (G0, dG)

#define WR1_OFF 0
#define WR2_OFF 864
#define WR3_OFF 19296
#define WR4_OFF 93024

// ------ merged prep: resize (blocks 0..1535) + tiled transposes (919) -------
// Transposes: conv repacks [oc][icp] -> [icp][oc], lin1 [oc][k] -> [k][oc].
__global__ void prep2_kernel(const float* __restrict__ img, float* __restrict__ xout,
                             const float* __restrict__ w1, const float* __restrict__ w2,
                             const float* __restrict__ w3, const float* __restrict__ w4,
                             const float* __restrict__ lw, float* __restrict__ wrep,
                             float* __restrict__ wT) {
    if (blockIdx.x < 1536) {
        int idx = blockIdx.x * 256 + threadIdx.x;
        int ox = idx & 255;
        int oy = (idx >> 8) & 255;
        int bc = idx >> 16;
        const float scale = 1023.0f / 255.0f;
        float py = oy * scale;
        int iy = (int)py; if (iy > 1022) iy = 1022;
        float fy = py - (float)iy;
        float px = ox * scale;
        int ix = (int)px; if (ix > 1022) ix = 1022;
        float fx = px - (float)ix;
        const float* p = img + ((long)bc << 20) + iy * 1024 + ix;
        float v00 = p[0], v01 = p[1], v10 = p[1024], v11 = p[1025];
        float c0 = v00 + fy * (v10 - v00);
        float c1 = v01 + fy * (v11 - v01);
        xout[idx] = c0 + fx * (c1 - c0);
        return;
    }

    __shared__ float t[32][33];
    const float* src; float* dst; int OC, K, bx, by;
    int id = blockIdx.x - 1536;
    if (id < 1)        { src = w1; dst = wrep + WR1_OFF; OC = 32;  K = 27;   bx = 0;        by = 0; }
    else if (id < 19)  { id -= 1;   src = w2; dst = wrep + WR2_OFF; OC = 64;  K = 288;  bx = id % 9;   by = id / 9; }
    else if (id < 91)  { id -= 19;  src = w3; dst = wrep + WR3_OFF; OC = 128; K = 576;  bx = id % 18;  by = id / 18; }
    else if (id < 379) { id -= 91;  src = w4; dst = wrep + WR4_OFF; OC = 256; K = 1152; bx = id % 36;  by = id / 36; }
    else               { id -= 379; src = lw; dst = wT;             OC = 128; K = 4320; bx = id % 135; by = id / 135; }

    int tx = threadIdx.x & 31, ty = threadIdx.x >> 5;
    int col0 = bx * 32, row0 = by * 32;
#pragma unroll
    for (int i = 0; i < 4; i++) {
        int r = row0 + ty + i * 8, c = col0 + tx;
        t[ty + i * 8][tx] = (c < K && r < OC) ? src[(long)r * K + c] : 0.f;
    }
    __syncthreads();
#pragma unroll
    for (int i = 0; i < 4; i++) {
        int c = col0 + ty + i * 8, r = row0 + tx;
        if (c < K && r < OC) dst[(long)c * OC + r] = t[tx][ty + i * 8];
    }
}

// --- stride-2 3x3 conv: 8oc x 4ow, wide input loads (.64+.128+.128), split-K -
template <int ICC, int OC, int H, bool FUSE>
__global__ __launch_bounds__(256, 2) void conv_v8(
    const float* __restrict__ in, const float* __restrict__ wrep,
    const float* __restrict__ bias, float* __restrict__ out, int ICtot) {
    constexpr int OH = H / 2;
    constexpr int OW = H / 2;
    constexpr int QW = OW / 4;
    constexpr int NOCG = OC / 8;
    constexpr int TOTAL = 2 * NOCG * OH * QW;
    constexpr int NOUT = 2 * OC * OH * OW;
    int idx = blockIdx.x * blockDim.x + threadIdx.x;
    if (idx >= TOTAL) return;
    int ks = blockIdx.y;
    int ic0 = ks * ICC;

    int ocg = idx % NOCG;
    int q = (idx / NOCG) % QW;
    int oh = (idx / (NOCG * QW)) % OH;
    int b = idx / (NOCG * QW * OH);
    int ow0 = q * 4;
    int oc0 = ocg * 8;
    int base = 2 * ow0;

    int rr[3];
#pragma unroll
    for (int kh = 0; kh < 3; kh++) { int r = 2 * oh - 1 + kh; rr[kh] = (r < 0) ? -r : r; }

    ull acc[4][4];
#pragma unroll
    for (int o2 = 0; o2 < 4; o2++) {
        ull bv = (ks == 0) ? pkpair(bias[oc0 + 2 * o2], bias[oc0 + 2 * o2 + 1]) : 0ull;
#pragma unroll
        for (int j = 0; j < 4; j++) acc[o2][j] = bv;
    }

    const float* wbase = wrep + (long)ic0 * 9 * OC + oc0;

    for (int ic = 0; ic < ICC; ic++) {
        const float* ip = in + (long)(b * ICtot + ic0 + ic) * H * H;
        const float* wp = wbase + (long)ic * 9 * OC;

        float v[3][10];
        if (base) {
#pragma unroll
            for (int kh = 0; kh < 3; kh++) {
                const float* rp = ip + rr[kh] * H + base;
                float2 a = __ldg((const float2*)(rp - 2));
                float4 m = __ldg((const float4*)rp);
                float4 e = __ldg((const float4*)(rp + 4));
                v[kh][0] = a.x; v[kh][1] = a.y;
                v[kh][2] = m.x; v[kh][3] = m.y; v[kh][4] = m.z; v[kh][5] = m.w;
                v[kh][6] = e.x; v[kh][7] = e.y; v[kh][8] = e.z; v[kh][9] = e.w;
            }
        } else {
#pragma unroll
            for (int kh = 0; kh < 3; kh++) {
                const float* rp = ip + rr[kh] * H;
                float4 m = __ldg((const float4*)rp);
                float4 e = __ldg((const float4*)(rp + 4));
                v[kh][2] = m.x; v[kh][3] = m.y; v[kh][4] = m.z; v[kh][5] = m.w;
                v[kh][6] = e.x; v[kh][7] = e.y; v[kh][8] = e.z; v[kh][9] = e.w;
                v[kh][1] = m.y;
                v[kh][0] = 0.f;
            }
        }

#pragma unroll
        for (int kh = 0; kh < 3; kh++) {
            ull xx[9];
#pragma unroll
            for (int i = 0; i < 9; i++) xx[i] = pk2(v[kh][i + 1]);
#pragma unroll
            for (int kw = 0; kw < 3; kw++) {
                const ulonglong2* w2p = (const ulonglong2*)(wp + (kh * 3 + kw) * OC);
                ulonglong2 wa = __ldg(w2p);
                ulonglong2 wb = __ldg(w2p + 1);
                ull wv[4] = {wa.x, wa.y, wb.x, wb.y};
#pragma unroll
                for (int o2 = 0; o2 < 4; o2++)
#pragma unroll
                    for (int j = 0; j < 4; j++)
                        acc[o2][j] = f2fma(wv[o2], xx[2 * j + kw], acc[o2][j]);
            }
        }
    }

    float* ob = out + (FUSE ? 0l : (long)ks * NOUT);
#pragma unroll
    for (int o2 = 0; o2 < 4; o2++) {
        float2 p0 = upk(acc[o2][0]), p1 = upk(acc[o2][1]), p2 = upk(acc[o2][2]), p3 = upk(acc[o2][3]);
        float ev0 = p0.x, ev1 = p1.x, ev2 = p2.x, ev3 = p3.x;
        float od0 = p0.y, od1 = p1.y, od2 = p2.y, od3 = p3.y;
        if (FUSE) {
            ev0 = silu_f(ev0); ev1 = silu_f(ev1); ev2 = silu_f(ev2); ev3 = silu_f(ev3);
            od0 = silu_f(od0); od1 = silu_f(od1); od2 = silu_f(od2); od3 = silu_f(od3);
        }
        long oe = ((long)(b * OC + oc0 + 2 * o2) * OH + oh) * OW + ow0;
        *(float4*)(ob + oe) = make_float4(ev0, ev1, ev2, ev3);
        *(float4*)(ob + oe + (long)OH * OW) = make_float4(od0, od1, od2, od3);
    }
}

// ------ split-K reduce + SiLU epilogue (2x float4/thread for MLP=8) ---------
__global__ void reduce_silu8_kernel(const float4* __restrict__ part, float4* __restrict__ out,
                                    int n4, int ks) {
    int t = blockIdx.x * blockDim.x + threadIdx.x;
    int idx = t * 2;
    if (idx >= n4) return;
    float4 s0 = part[idx];
    float4 s1 = part[idx + 1];
    for (int k = 1; k < ks; k++) {
        float4 p0 = part[k * n4 + idx];
        float4 p1 = part[k * n4 + idx + 1];
        s0.x += p0.x; s0.y += p0.y; s0.z += p0.z; s0.w += p0.w;
        s1.x += p1.x; s1.y += p1.y; s1.z += p1.z; s1.w += p1.w;
    }
    s0.x = silu_f(s0.x); s0.y = silu_f(s0.y); s0.z = silu_f(s0.z); s0.w = silu_f(s0.w);
    s1.x = silu_f(s1.x); s1.y = silu_f(s1.y); s1.z = silu_f(s1.z); s1.w = silu_f(s1.w);
    out[idx] = s0;
    out[idx + 1] = s1;
}

// ---------- merged avg pools: sub-warp sized per pool window -----------------
// c1(k=16): 32 thr/out, c2(k=8): 8 thr/out, c3(k=4): 4 thr/out, c4(k=2): 1 thr.
__global__ void pool_v2_kernel(const float* __restrict__ c1, const float* __restrict__ c2,
                               const float* __restrict__ c3, const float* __restrict__ c4,
                               float* __restrict__ feat) {
    int gid = blockIdx.x * 256 + threadIdx.x;
    if (gid < 131072) {                       // c1: warp per output
        int lane = gid & 31;
        int o = gid >> 5;
        int x = o & 7, y = (o >> 3) & 7, c = (o >> 6) % 32, b = o / 2048;
        const float* base = c1 + ((long)(b * 32 + c) * 128 + y * 16) * 128 + x * 16;
        float s = 0.f;
#pragma unroll
        for (int j = lane; j < 256; j += 32) s += base[(j >> 4) * 128 + (j & 15)];
#pragma unroll
        for (int off = 16; off > 0; off >>= 1) s += __shfl_down_sync(0xffffffffu, s, off);
        if (lane == 0) feat[((b * 480 + c) * 8 + y) * 8 + x] = s * (1.f / 256.f);
    } else if (gid < 196608) {                // c2: 8 threads per output
        int g = gid - 131072;
        int s8 = g & 7;
        int o = g >> 3;
        int x = o & 7, y = (o >> 3) & 7, c = (o >> 6) % 64, b = o / 4096;
        const float* base = c2 + ((long)(b * 64 + c) * 64 + y * 8) * 64 + x * 8 + s8;
        float s = 0.f;
#pragma unroll
        for (int t = 0; t < 8; t++) s += base[t * 64];
        s += __shfl_down_sync(0xffffffffu, s, 4, 8);
        s += __shfl_down_sync(0xffffffffu, s, 2, 8);
        s += __shfl_down_sync(0xffffffffu, s, 1, 8);
        if (s8 == 0) feat[((b * 480 + 32 + c) * 8 + y) * 8 + x] = s * (1.f / 64.f);
    } else if (gid < 262144) {                // c3: 4 threads per output
        int g = gid - 196608;
        int s4 = g & 3;
        int o = g >> 2;
        int x = o & 7, y = (o >> 3) & 7, c = (o >> 6) % 128, b = o / 8192;
        const float* base = c3 + ((long)(b * 128 + c) * 32 + y * 4) * 32 + x * 4 + s4;
        float s = 0.f;
#pragma unroll
        for (int t = 0; t < 4; t++) s += base[t * 32];
        s += __shfl_down_sync(0xffffffffu, s, 2, 4);
        s += __shfl_down_sync(0xffffffffu, s, 1, 4);
        if (s4 == 0) feat[((b * 480 + 96 + c) * 8 + y) * 8 + x] = s * (1.f / 16.f);
    } else if (gid < 294912) {                // c4: 1 thread per output
        int o = gid - 262144;
        int x = o & 7, y = (o >> 3) & 7, c = (o >> 6) % 256, b = o / 16384;
        const float* base = c4 + ((long)(b * 256 + c) * 16 + y * 2) * 16 + x * 2;
        float s = base[0] + base[1] + base[16] + base[17];
        feat[((b * 480 + 224 + c) * 8 + y) * 8 + x] = s * 0.25f;
    }
}

// ----------------- lin1: 3x3 reflect conv 480->128 on 8x8 -------------------
__global__ __launch_bounds__(128) void lin1_kernel(const float* __restrict__ feat,
                                                   const float* __restrict__ wT,
                                                   float* __restrict__ part) {
    __shared__ float slab[16 * 3 * 8];
    int kc = blockIdx.x;
    int oh = blockIdx.y;
    int b = blockIdx.z;
    int t = threadIdx.x;
    int ic0 = kc * 16;

    int ihs[3];
#pragma unroll
    for (int kh = 0; kh < 3; kh++) {
        int r = oh - 1 + kh;
        if (r < 0) r = -r;
        if (r > 7) r = 14 - r;
        ihs[kh] = r;
    }
    for (int j = t; j < 384; j += 128) {
        int icl = j / 24;
        int rem = j % 24;
        int r = rem / 8, col = rem % 8;
        slab[j] = feat[((b * 480 + ic0 + icl) * 8 + ihs[r]) * 8 + col];
    }
    __syncthreads();

    float acc[8];
#pragma unroll
    for (int ow = 0; ow < 8; ow++) acc[ow] = 0.f;

    const int IWT[10] = {1, 0, 1, 2, 3, 4, 5, 6, 7, 6};
#pragma unroll 2
    for (int icl = 0; icl < 16; icl++) {
        float rv[3][8];
#pragma unroll
        for (int r = 0; r < 3; r++)
#pragma unroll
            for (int col = 0; col < 8; col++) rv[r][col] = slab[icl * 24 + r * 8 + col];
#pragma unroll
        for (int kh = 0; kh < 3; kh++)
#pragma unroll
            for (int kw = 0; kw < 3; kw++) {
                float wv = __ldg(wT + (long)((ic0 + icl) * 9 + kh * 3 + kw) * 128 + t);
#pragma unroll
                for (int ow = 0; ow < 8; ow++) acc[ow] += wv * rv[kh][IWT[ow + kw]];
            }
    }
    int base = (((kc * 2 + b) * 128 + t) * 8 + oh) * 8;
#pragma unroll
    for (int ow = 0; ow < 8; ow++) part[base + ow] = acc[ow];
}

__global__ void lin1_reduce_kernel(const float* __restrict__ part,
                                   const float* __restrict__ bias, float* __restrict__ h1) {
    int idx = blockIdx.x * blockDim.x + threadIdx.x;
    if (idx >= 16384) return;
    int oc = (idx >> 6) & 127;
    float s = bias[oc];
#pragma unroll 6
    for (int kc = 0; kc < 30; kc++) s += part[kc * 16384 + idx];
    h1[idx] = silu_f(s);
}

// ---- fused lin2 (1x1 conv 128->27 + sigmoid) + G table build ---------------
__global__ __launch_bounds__(256) void gprep2_kernel(
    const float* __restrict__ h1, const float* __restrict__ w2,
    const float* __restrict__ b2, const float* __restrict__ luts,
    float* __restrict__ G) {
    int gy = blockIdx.x & 7;
    int c = (blockIdx.x >> 3) % 3;
    int b = blockIdx.x / 24;
    __shared__ float sh1[128][8];
    __shared__ float wk[9][8];
    int tid = threadIdx.x;
    for (int j = tid; j < 1024; j += 256) {
        int ic = j >> 3, gx = j & 7;
        sh1[ic][gx] = h1[(b * 128 + ic) * 64 + gy * 8 + gx];
    }
    __syncthreads();
    if (tid < 72) {
        int k = tid >> 3, gx = tid & 7;
        float acc = b2[c * 9 + k];
        const float* wp = w2 + (c * 9 + k) * 128;
#pragma unroll 8
        for (int ic = 0; ic < 128; ic++) acc = fmaf(__ldg(wp + ic), sh1[ic][gx], acc);
        wk[k][gx] = sigm_f(acc);
    }
    __syncthreads();
    for (int j = tid; j < 2048; j += 256) {
        int gx = j >> 8;
        int i = j & 255;
        float g0 = 0.f, g1 = 0.f;
#pragma unroll
        for (int k = 0; k < 9; k++) {
            const float* lp = luts + (c * 9 + k) * 256;
            float l0 = lp[i];
            float l1 = (i < 255) ? lp[i + 1] : l0;
            g0 = fmaf(wk[k][gx], l0, g0);
            g1 = fmaf(wk[k][gx], l1, g1);
        }
        long o = ((((long)(b * 3 + c) * 8 + gy) * 8 + gx) * 256 + i) * 2;
        G[o] = g0;
        G[o + 1] = g1 - g0;
    }
}

// ----- final: per-pixel 4-corner gather, channel-split blocks (4 CTA/SM) -----
__global__ __launch_bounds__(512) void final_v4(const float* __restrict__ img,
                                                const float* __restrict__ G,
                                                float* __restrict__ out) {
    extern __shared__ float sG[];  // 3 gyl rows x 2048 float2 = 49152 B
    int rg = blockIdx.x;    // 0..63 (16 rows each)
    int c = blockIdx.y;     // channel
    int b = blockIdx.z;
    int tid = threadIdx.x;
    int h0 = rg * 16;
    const float sc = 7.0f / 1023.0f;

    int g0row = (int)(h0 * sc); if (g0row > 6) g0row = 6;
    int gy_base = (g0row > 5) ? 5 : g0row;

    float4* sG4 = (float4*)sG;
    for (int j = tid; j < 3072; j += 512) {
        int gyl = j >> 10;
        int r = j & 1023;
        const float4* Gp = (const float4*)(G + ((long)((b * 3 + c) * 8 + gy_base + gyl)) * 4096);
        sG4[j] = Gp[r];
    }
    __syncthreads();

    int w0 = tid * 2;
    int gxp[2]; float fwp[2];
#pragma unroll
    for (int px = 0; px < 2; px++) {
        float pwv = (w0 + px) * sc;
        int gx = (int)pwv; if (gx > 6) gx = 6;
        gxp[px] = gx;
        fwp[px] = pwv - (float)gx;
    }

    const float2* sgp = (const float2*)sG;
    long cb = ((long)(b * 3 + c) << 20);

    for (int r = 0; r < 16; r++) {
        int h = h0 + r;
        float ph = h * sc;
        int gy0 = (int)ph; if (gy0 > 6) gy0 = 6;
        float fh = ph - (float)gy0;
        int gyl = gy0 - gy_base;

        long ib = cb + ((long)h << 10) + w0;
        float2 iv = *(const float2*)(img + ib);
        float2 res;
        const float2* crow = sgp + gyl * 2048;
#pragma unroll
        for (int px = 0; px < 2; px++) {
            float v = px ? iv.y : iv.x;
            float p = fminf(fmaxf(v, 0.f), 1.f) * 255.0f;
            int i0 = (int)p; if (i0 > 254) i0 = 254;
            float fr = p - (float)i0;
            const float2* b00 = crow + gxp[px] * 256;
            float2 A = b00[i0];
            float2 Bv = b00[256 + i0];
            float2 Cv = b00[2048 + i0];
            float2 Dv = b00[2048 + 256 + i0];
            float va = fmaf(fr, A.y, A.x);
            float vb = fmaf(fr, Bv.y, Bv.x);
            float vc = fmaf(fr, Cv.y, Cv.x);
            float vd = fmaf(fr, Dv.y, Dv.x);
            float fw = fwp[px];
            float top = fmaf(fw, vb - va, va);
            float bot = fmaf(fw, vd - vc, vc);
            float rv = fmaf(fh, bot - top, top);
            rv = fminf(fmaxf(rv, 0.f), 1.f);
            if (px) res.y = rv; else res.x = rv;
        }
        *(float2*)(out + ib) = res;
    }
}

// --------------------------------- launch ----------------------------------
extern "C" void kernel_launch(void* const* d_in, const int* in_sizes, int n_in,
                              void* d_out, int out_size) {
    const float* img     = (const float*)d_in[0];
    const float* conv1_w = (const float*)d_in[1];
    const float* conv1_b = (const float*)d_in[2];
    const float* conv2_w = (const float*)d_in[3];
    const float* conv2_b = (const float*)d_in[4];
    const float* conv3_w = (const float*)d_in[5];
    const float* conv3_b = (const float*)d_in[6];
    const float* conv4_w = (const float*)d_in[7];
    const float* conv4_b = (const float*)d_in[8];
    const float* lin1_w  = (const float*)d_in[9];
    const float* lin1_b  = (const float*)d_in[10];
    const float* lin2_w  = (const float*)d_in[11];
    const float* lin2_b  = (const float*)d_in[12];
    const float* luts    = (const float*)d_in[13];
    float* out = (float*)d_out;

    float *px, *pc1, *pc2, *pc3, *pc4, *pfeat, *ph1, *pwT, *plp, *pcp, *pwr, *pG;
    cudaGetSymbolAddress((void**)&px, g_x);
    cudaGetSymbolAddress((void**)&pc1, g_c1);
    cudaGetSymbolAddress((void**)&pc2, g_c2);
    cudaGetSymbolAddress((void**)&pc3, g_c3);
    cudaGetSymbolAddress((void**)&pc4, g_c4);
    cudaGetSymbolAddress((void**)&pfeat, g_feat);
    cudaGetSymbolAddress((void**)&ph1, g_h1);
    cudaGetSymbolAddress((void**)&pwT, g_wT);
    cudaGetSymbolAddress((void**)&plp, g_lpart);
    cudaGetSymbolAddress((void**)&pcp, g_cpart);
    cudaGetSymbolAddress((void**)&pwr, g_wrep);
    cudaGetSymbolAddress((void**)&pG, g_G);

    cudaFuncSetAttribute(final_v4, cudaFuncAttributeMaxDynamicSharedMemorySize, 49152);

    // 0. merged prep: resize + tiled weight transposes
    prep2_kernel<<<1536 + 919, 256>>>(img, px, conv1_w, conv2_w, conv3_w,
                                      conv4_w, lin1_w, pwr, pwT);

    // 2-5. conv stack (wide-load conv_v8, split-K)
    conv_v8<3, 32, 256, true><<<dim3(256, 1), 128>>>(px, pwr + WR1_OFF, conv1_b, pc1, 3);

    conv_v8<8, 64, 128, false><<<dim3(64, 4), 256>>>(pc1, pwr + WR2_OFF, conv2_b, pcp, 32);
    reduce_silu8_kernel<<<256, 256>>>((const float4*)pcp, (float4*)pc2, 131072, 4);

    conv_v8<8, 128, 64, false><<<dim3(32, 8), 256>>>(pc2, pwr + WR3_OFF, conv3_b, pcp, 64);
    reduce_silu8_kernel<<<128, 256>>>((const float4*)pcp, (float4*)pc3, 65536, 8);

    conv_v8<8, 256, 32, false><<<dim3(16, 16), 256>>>(pc3, pwr + WR4_OFF, conv4_b, pcp, 128);
    reduce_silu8_kernel<<<64, 256>>>((const float4*)pcp, (float4*)pc4, 32768, 16);

    // 6. multi-scale avg pools (sub-warp sized)
    pool_v2_kernel<<<1152, 256>>>(pc1, pc2, pc3, pc4, pfeat);

    // 7. lin1 (480->128, 3x3 reflect, SiLU), split-K x30
    lin1_kernel<<<dim3(30, 8, 2), 128>>>(pfeat, pwT, plp);
    lin1_reduce_kernel<<<64, 256>>>(plp, lin1_b, ph1);

    // 8+9. fused lin2 + G table
    gprep2_kernel<<<48, 256>>>(ph1, lin2_w, lin2_b, luts, pG);

    // 10. final: 4-corner gather + clip (channel-split, 4 CTAs/SM)
    final_v4<<<dim3(64, 3, 2), 512, 49152>>>(img, pG, out);
}

// round 14
// speedup vs baseline: 1.2216x; 1.0377x over previous
#include <cuda_runtime.h>
#include <math.h>

#define DINL __device__ __forceinline__
typedef unsigned long long ull;

// ---- fast silu: software exp2 (FMA poly) + rcp.approx + 1 Newton (1 MUFU) --
// rel err ~3e-6; avoids EX2+RCP double-MUFU (or software-div) cost of expf.
DINL float fast_exp_neg(float x) {  // e^{-x}
    float z = -x * 1.44269504f;                       // log2(e)
    z = fmaxf(fminf(z, 126.f), -126.f);
    float t = z + 12582912.f;                         // round-to-nearest trick
    int ni = __float_as_int(t) - 0x4B400000;
    float f = z - (t - 12582912.f);                   // f in [-0.5, 0.5]
    float p = 1.8775767e-3f;
    p = fmaf(p, f, 8.9893397e-3f);
    p = fmaf(p, f, 5.5802381e-2f);
    p = fmaf(p, f, 2.4015947e-1f);
    p = fmaf(p, f, 6.9314718e-1f);
    p = fmaf(p, f, 1.0f);
    float sc = __int_as_float((ni + 127) << 23);
    return p * sc;
}
DINL float rcp_nr(float d) {
    float r;
    asm("rcp.approx.ftz.f32 %0,%1;" : "=f"(r) : "f"(d));
    return r * (2.f - d * r);                         // 1 Newton step
}
DINL float silu_f(float x) { return x * rcp_nr(1.f + fast_exp_neg(x)); }
DINL float sigm_f(float x) { return rcp_nr(1.f + fast_exp_neg(x)); }

// ---------------- packed f32x2 helpers (sm_100+) ----------------
DINL ull pk2(float x) { ull r; asm("mov.b64 %0,{%1,%1};" : "=l"(r) : "f"(x)); return r; }
DINL ull pkpair(float a, float b) { ull r; asm("mov.b64 %0,{%1,%2};" : "=l"(r) : "f"(a), "f"(b)); return r; }
DINL ull f2fma(ull a, ull b, ull c) {
    ull d; asm("fma.rn.f32x2 %0,%1,%2,%3;" : "=l"(d) : "l"(a), "l"(b), "l"(c)); return d;
}
DINL float2 upk(ull a) { float lo, hi; asm("mov.b64 {%0,%1},%2;" : "=f"(lo), "=f"(hi) : "l"(a)); return make_float2(lo, hi); }

// ------------------------- scratch (device globals) ------------------------
__device__ float g_x[2 * 3 * 256 * 256];
__device__ float g_c1[2 * 32 * 128 * 128];
__device__ float g_c2[2 * 64 * 64 * 64];
__device__ float g_c3[2 * 128 * 32 * 32];
__device__ float g_c4[2 * 256 * 16 * 16];
__device__ float g_feat[2 * 480 * 8 * 8];
__device__ float g_h1[2 * 128 * 8 * 8];
__device__ float g_wT[4320 * 128];
__device__ float g_lpart[30 * 2 * 128 * 8 * 8];
__device__ float g_cpart[2097152];
__device__ float g_wrep[387936];
__device__ float g_G[2 * 3 * 8 * 8 * 256 * 2];   // fused weight*LUT table (G0, dG)

#define WR1_OFF 0
#define WR2_OFF 864
#define WR3_OFF 19296
#define WR4_OFF 93024

// ------ merged prep: resize (blocks 0..1535) + tiled transposes (919) -------
__global__ void prep2_kernel(const float* __restrict__ img, float* __restrict__ xout,
                             const float* __restrict__ w1, const float* __restrict__ w2,
                             const float* __restrict__ w3, const float* __restrict__ w4,
                             const float* __restrict__ lw, float* __restrict__ wrep,
                             float* __restrict__ wT) {
    if (blockIdx.x < 1536) {
        int idx = blockIdx.x * 256 + threadIdx.x;
        int ox = idx & 255;
        int oy = (idx >> 8) & 255;
        int bc = idx >> 16;
        const float scale = 1023.0f / 255.0f;
        float py = oy * scale;
        int iy = (int)py; if (iy > 1022) iy = 1022;
        float fy = py - (float)iy;
        float px = ox * scale;
        int ix = (int)px; if (ix > 1022) ix = 1022;
        float fx = px - (float)ix;
        const float* p = img + ((long)bc << 20) + iy * 1024 + ix;
        float v00 = p[0], v01 = p[1], v10 = p[1024], v11 = p[1025];
        float c0 = v00 + fy * (v10 - v00);
        float c1 = v01 + fy * (v11 - v01);
        xout[idx] = c0 + fx * (c1 - c0);
        return;
    }

    __shared__ float t[32][33];
    const float* src; float* dst; int OC, K, bx, by;
    int id = blockIdx.x - 1536;
    if (id < 1)        { src = w1; dst = wrep + WR1_OFF; OC = 32;  K = 27;   bx = 0;        by = 0; }
    else if (id < 19)  { id -= 1;   src = w2; dst = wrep + WR2_OFF; OC = 64;  K = 288;  bx = id % 9;   by = id / 9; }
    else if (id < 91)  { id -= 19;  src = w3; dst = wrep + WR3_OFF; OC = 128; K = 576;  bx = id % 18;  by = id / 18; }
    else if (id < 379) { id -= 91;  src = w4; dst = wrep + WR4_OFF; OC = 256; K = 1152; bx = id % 36;  by = id / 36; }
    else               { id -= 379; src = lw; dst = wT;             OC = 128; K = 4320; bx = id % 135; by = id / 135; }

    int tx = threadIdx.x & 31, ty = threadIdx.x >> 5;
    int col0 = bx * 32, row0 = by * 32;
#pragma unroll
    for (int i = 0; i < 4; i++) {
        int r = row0 + ty + i * 8, c = col0 + tx;
        t[ty + i * 8][tx] = (c < K && r < OC) ? src[(long)r * K + c] : 0.f;
    }
    __syncthreads();
#pragma unroll
    for (int i = 0; i < 4; i++) {
        int c = col0 + ty + i * 8, r = row0 + tx;
        if (c < K && r < OC) dst[(long)c * OC + r] = t[tx][ty + i * 8];
    }
}

// --- stride-2 3x3 conv: 8oc x 4ow, wide input loads (.64+.128+.128), split-K -
template <int ICC, int OC, int H, bool FUSE>
__global__ __launch_bounds__(256, 2) void conv_v8(
    const float* __restrict__ in, const float* __restrict__ wrep,
    const float* __restrict__ bias, float* __restrict__ out, int ICtot) {
    constexpr int OH = H / 2;
    constexpr int OW = H / 2;
    constexpr int QW = OW / 4;
    constexpr int NOCG = OC / 8;
    constexpr int TOTAL = 2 * NOCG * OH * QW;
    constexpr int NOUT = 2 * OC * OH * OW;
    int idx = blockIdx.x * blockDim.x + threadIdx.x;
    if (idx >= TOTAL) return;
    int ks = blockIdx.y;
    int ic0 = ks * ICC;

    int ocg = idx % NOCG;
    int q = (idx / NOCG) % QW;
    int oh = (idx / (NOCG * QW)) % OH;
    int b = idx / (NOCG * QW * OH);
    int ow0 = q * 4;
    int oc0 = ocg * 8;
    int base = 2 * ow0;

    int rr[3];
#pragma unroll
    for (int kh = 0; kh < 3; kh++) { int r = 2 * oh - 1 + kh; rr[kh] = (r < 0) ? -r : r; }

    ull acc[4][4];
#pragma unroll
    for (int o2 = 0; o2 < 4; o2++) {
        ull bv = (ks == 0) ? pkpair(bias[oc0 + 2 * o2], bias[oc0 + 2 * o2 + 1]) : 0ull;
#pragma unroll
        for (int j = 0; j < 4; j++) acc[o2][j] = bv;
    }

    const float* wbase = wrep + (long)ic0 * 9 * OC + oc0;

    for (int ic = 0; ic < ICC; ic++) {
        const float* ip = in + (long)(b * ICtot + ic0 + ic) * H * H;
        const float* wp = wbase + (long)ic * 9 * OC;

        float v[3][10];
        if (base) {
#pragma unroll
            for (int kh = 0; kh < 3; kh++) {
                const float* rp = ip + rr[kh] * H + base;
                float2 a = __ldg((const float2*)(rp - 2));
                float4 m = __ldg((const float4*)rp);
                float4 e = __ldg((const float4*)(rp + 4));
                v[kh][0] = a.x; v[kh][1] = a.y;
                v[kh][2] = m.x; v[kh][3] = m.y; v[kh][4] = m.z; v[kh][5] = m.w;
                v[kh][6] = e.x; v[kh][7] = e.y; v[kh][8] = e.z; v[kh][9] = e.w;
            }
        } else {
#pragma unroll
            for (int kh = 0; kh < 3; kh++) {
                const float* rp = ip + rr[kh] * H;
                float4 m = __ldg((const float4*)rp);
                float4 e = __ldg((const float4*)(rp + 4));
                v[kh][2] = m.x; v[kh][3] = m.y; v[kh][4] = m.z; v[kh][5] = m.w;
                v[kh][6] = e.x; v[kh][7] = e.y; v[kh][8] = e.z; v[kh][9] = e.w;
                v[kh][1] = m.y;
                v[kh][0] = 0.f;
            }
        }

#pragma unroll
        for (int kh = 0; kh < 3; kh++) {
            ull xx[9];
#pragma unroll
            for (int i = 0; i < 9; i++) xx[i] = pk2(v[kh][i + 1]);
#pragma unroll
            for (int kw = 0; kw < 3; kw++) {
                const ulonglong2* w2p = (const ulonglong2*)(wp + (kh * 3 + kw) * OC);
                ulonglong2 wa = __ldg(w2p);
                ulonglong2 wb = __ldg(w2p + 1);
                ull wv[4] = {wa.x, wa.y, wb.x, wb.y};
#pragma unroll
                for (int o2 = 0; o2 < 4; o2++)
#pragma unroll
                    for (int j = 0; j < 4; j++)
                        acc[o2][j] = f2fma(wv[o2], xx[2 * j + kw], acc[o2][j]);
            }
        }
    }

    float* ob = out + (FUSE ? 0l : (long)ks * NOUT);
#pragma unroll
    for (int o2 = 0; o2 < 4; o2++) {
        float2 p0 = upk(acc[o2][0]), p1 = upk(acc[o2][1]), p2 = upk(acc[o2][2]), p3 = upk(acc[o2][3]);
        float ev0 = p0.x, ev1 = p1.x, ev2 = p2.x, ev3 = p3.x;
        float od0 = p0.y, od1 = p1.y, od2 = p2.y, od3 = p3.y;
        if (FUSE) {
            ev0 = silu_f(ev0); ev1 = silu_f(ev1); ev2 = silu_f(ev2); ev3 = silu_f(ev3);
            od0 = silu_f(od0); od1 = silu_f(od1); od2 = silu_f(od2); od3 = silu_f(od3);
        }
        long oe = ((long)(b * OC + oc0 + 2 * o2) * OH + oh) * OW + ow0;
        *(float4*)(ob + oe) = make_float4(ev0, ev1, ev2, ev3);
        *(float4*)(ob + oe + (long)OH * OW) = make_float4(od0, od1, od2, od3);
    }
}

// -------------- split-K reduce + SiLU epilogue (float4 streams) -------------
__global__ void reduce_silu4_kernel(const float4* __restrict__ part, float4* __restrict__ out,
                                    int n4, int ks) {
    int idx = blockIdx.x * blockDim.x + threadIdx.x;
    if (idx >= n4) return;
    float4 s = part[idx];
    for (int k = 1; k < ks; k++) {
        float4 p = part[k * n4 + idx];
        s.x += p.x; s.y += p.y; s.z += p.z; s.w += p.w;
    }
    s.x = silu_f(s.x); s.y = silu_f(s.y); s.z = silu_f(s.z); s.w = silu_f(s.w);
    out[idx] = s;
}

// ---------- merged avg pools: sub-warp sized per pool window -----------------
__global__ void pool_v2_kernel(const float* __restrict__ c1, const float* __restrict__ c2,
                               const float* __restrict__ c3, const float* __restrict__ c4,
                               float* __restrict__ feat) {
    int gid = blockIdx.x * 256 + threadIdx.x;
    if (gid < 131072) {                       // c1: warp per output
        int lane = gid & 31;
        int o = gid >> 5;
        int x = o & 7, y = (o >> 3) & 7, c = (o >> 6) % 32, b = o / 2048;
        const float* base = c1 + ((long)(b * 32 + c) * 128 + y * 16) * 128 + x * 16;
        float s = 0.f;
#pragma unroll
        for (int j = lane; j < 256; j += 32) s += base[(j >> 4) * 128 + (j & 15)];
#pragma unroll
        for (int off = 16; off > 0; off >>= 1) s += __shfl_down_sync(0xffffffffu, s, off);
        if (lane == 0) feat[((b * 480 + c) * 8 + y) * 8 + x] = s * (1.f / 256.f);
    } else if (gid < 196608) {                // c2: 8 threads per output
        int g = gid - 131072;
        int s8 = g & 7;
        int o = g >> 3;
        int x = o & 7, y = (o >> 3) & 7, c = (o >> 6) % 64, b = o / 4096;
        const float* base = c2 + ((long)(b * 64 + c) * 64 + y * 8) * 64 + x * 8 + s8;
        float s = 0.f;
#pragma unroll
        for (int t = 0; t < 8; t++) s += base[t * 64];
        s += __shfl_down_sync(0xffffffffu, s, 4, 8);
        s += __shfl_down_sync(0xffffffffu, s, 2, 8);
        s += __shfl_down_sync(0xffffffffu, s, 1, 8);
        if (s8 == 0) feat[((b * 480 + 32 + c) * 8 + y) * 8 + x] = s * (1.f / 64.f);
    } else if (gid < 262144) {                // c3: 4 threads per output
        int g = gid - 196608;
        int s4 = g & 3;
        int o = g >> 2;
        int x = o & 7, y = (o >> 3) & 7, c = (o >> 6) % 128, b = o / 8192;
        const float* base = c3 + ((long)(b * 128 + c) * 32 + y * 4) * 32 + x * 4 + s4;
        float s = 0.f;
#pragma unroll
        for (int t = 0; t < 4; t++) s += base[t * 32];
        s += __shfl_down_sync(0xffffffffu, s, 2, 4);
        s += __shfl_down_sync(0xffffffffu, s, 1, 4);
        if (s4 == 0) feat[((b * 480 + 96 + c) * 8 + y) * 8 + x] = s * (1.f / 16.f);
    } else if (gid < 294912) {                // c4: 1 thread per output
        int o = gid - 262144;
        int x = o & 7, y = (o >> 3) & 7, c = (o >> 6) % 256, b = o / 16384;
        const float* base = c4 + ((long)(b * 256 + c) * 16 + y * 2) * 16 + x * 2;
        float s = base[0] + base[1] + base[16] + base[17];
        feat[((b * 480 + 224 + c) * 8 + y) * 8 + x] = s * 0.25f;
    }
}

// ----------------- lin1: 3x3 reflect conv 480->128 on 8x8 -------------------
__global__ __launch_bounds__(128) void lin1_kernel(const float* __restrict__ feat,
                                                   const float* __restrict__ wT,
                                                   float* __restrict__ part) {
    __shared__ float slab[16 * 3 * 8];
    int kc = blockIdx.x;
    int oh = blockIdx.y;
    int b = blockIdx.z;
    int t = threadIdx.x;
    int ic0 = kc * 16;

    int ihs[3];
#pragma unroll
    for (int kh = 0; kh < 3; kh++) {
        int r = oh - 1 + kh;
        if (r < 0) r = -r;
        if (r > 7) r = 14 - r;
        ihs[kh] = r;
    }
    for (int j = t; j < 384; j += 128) {
        int icl = j / 24;
        int rem = j % 24;
        int r = rem / 8, col = rem % 8;
        slab[j] = feat[((b * 480 + ic0 + icl) * 8 + ihs[r]) * 8 + col];
    }
    __syncthreads();

    float acc[8];
#pragma unroll
    for (int ow = 0; ow < 8; ow++) acc[ow] = 0.f;

    const int IWT[10] = {1, 0, 1, 2, 3, 4, 5, 6, 7, 6};
#pragma unroll 2
    for (int icl = 0; icl < 16; icl++) {
        float rv[3][8];
#pragma unroll
        for (int r = 0; r < 3; r++)
#pragma unroll
            for (int col = 0; col < 8; col++) rv[r][col] = slab[icl * 24 + r * 8 + col];
#pragma unroll
        for (int kh = 0; kh < 3; kh++)
#pragma unroll
            for (int kw = 0; kw < 3; kw++) {
                float wv = __ldg(wT + (long)((ic0 + icl) * 9 + kh * 3 + kw) * 128 + t);
#pragma unroll
                for (int ow = 0; ow < 8; ow++) acc[ow] += wv * rv[kh][IWT[ow + kw]];
            }
    }
    int base = (((kc * 2 + b) * 128 + t) * 8 + oh) * 8;
#pragma unroll
    for (int ow = 0; ow < 8; ow++) part[base + ow] = acc[ow];
}

__global__ void lin1_reduce_kernel(const float* __restrict__ part,
                                   const float* __restrict__ bias, float* __restrict__ h1) {
    int idx = blockIdx.x * blockDim.x + threadIdx.x;
    if (idx >= 16384) return;
    int oc = (idx >> 6) & 127;
    float s = bias[oc];
#pragma unroll 6
    for (int kc = 0; kc < 30; kc++) s += part[kc * 16384 + idx];
    h1[idx] = silu_f(s);
}

// ---- fused lin2 (1x1 conv 128->27 + sigmoid) + G table build ---------------
__global__ __launch_bounds__(256) void gprep2_kernel(
    const float* __restrict__ h1, const float* __restrict__ w2,
    const float* __restrict__ b2, const float* __restrict__ luts,
    float* __restrict__ G) {
    int gy = blockIdx.x & 7;
    int c = (blockIdx.x >> 3) % 3;
    int b = blockIdx.x / 24;
    __shared__ float sh1[128][8];
    __shared__ float wk[9][8];
    int tid = threadIdx.x;
    for (int j = tid; j < 1024; j += 256) {
        int ic = j >> 3, gx = j & 7;
        sh1[ic][gx] = h1[(b * 128 + ic) * 64 + gy * 8 + gx];
    }
    __syncthreads();
    if (tid < 72) {
        int k = tid >> 3, gx = tid & 7;
        float acc = b2[c * 9 + k];
        const float* wp = w2 + (c * 9 + k) * 128;
#pragma unroll 8
        for (int ic = 0; ic < 128; ic++) acc = fmaf(__ldg(wp + ic), sh1[ic][gx], acc);
        wk[k][gx] = sigm_f(acc);
    }
    __syncthreads();
    for (int j = tid; j < 2048; j += 256) {
        int gx = j >> 8;
        int i = j & 255;
        float g0 = 0.f, g1 = 0.f;
#pragma unroll
        for (int k = 0; k < 9; k++) {
            const float* lp = luts + (c * 9 + k) * 256;
            float l0 = lp[i];
            float l1 = (i < 255) ? lp[i + 1] : l0;
            g0 = fmaf(wk[k][gx], l0, g0);
            g1 = fmaf(wk[k][gx], l1, g1);
        }
        long o = ((((long)(b * 3 + c) * 8 + gy) * 8 + gx) * 256 + i) * 2;
        G[o] = g0;
        G[o + 1] = g1 - g0;
    }
}

// ----- final: per-pixel 4-corner gather, channel-split blocks (4 CTA/SM) -----
__global__ __launch_bounds__(512) void final_v4(const float* __restrict__ img,
                                                const float* __restrict__ G,
                                                float* __restrict__ out) {
    extern __shared__ float sG[];  // 3 gyl rows x 2048 float2 = 49152 B
    int rg = blockIdx.x;
    int c = blockIdx.y;
    int b = blockIdx.z;
    int tid = threadIdx.x;
    int h0 = rg * 16;
    const float sc = 7.0f / 1023.0f;

    int g0row = (int)(h0 * sc); if (g0row > 6) g0row = 6;
    int gy_base = (g0row > 5) ? 5 : g0row;

    float4* sG4 = (float4*)sG;
    for (int j = tid; j < 3072; j += 512) {
        int gyl = j >> 10;
        int r = j & 1023;
        const float4* Gp = (const float4*)(G + ((long)((b * 3 + c) * 8 + gy_base + gyl)) * 4096);
        sG4[j] = Gp[r];
    }
    __syncthreads();

    int w0 = tid * 2;
    int gxp[2]; float fwp[2];
#pragma unroll
    for (int px = 0; px < 2; px++) {
        float pwv = (w0 + px) * sc;
        int gx = (int)pwv; if (gx > 6) gx = 6;
        gxp[px] = gx;
        fwp[px] = pwv - (float)gx;
    }

    const float2* sgp = (const float2*)sG;
    long cb = ((long)(b * 3 + c) << 20);

    for (int r = 0; r < 16; r++) {
        int h = h0 + r;
        float ph = h * sc;
        int gy0 = (int)ph; if (gy0 > 6) gy0 = 6;
        float fh = ph - (float)gy0;
        int gyl = gy0 - gy_base;

        long ib = cb + ((long)h << 10) + w0;
        float2 iv = *(const float2*)(img + ib);
        float2 res;
        const float2* crow = sgp + gyl * 2048;
#pragma unroll
        for (int px = 0; px < 2; px++) {
            float v = px ? iv.y : iv.x;
            float p = fminf(fmaxf(v, 0.f), 1.f) * 255.0f;
            int i0 = (int)p; if (i0 > 254) i0 = 254;
            float fr = p - (float)i0;
            const float2* b00 = crow + gxp[px] * 256;
            float2 A = b00[i0];
            float2 Bv = b00[256 + i0];
            float2 Cv = b00[2048 + i0];
            float2 Dv = b00[2048 + 256 + i0];
            float va = fmaf(fr, A.y, A.x);
            float vb = fmaf(fr, Bv.y, Bv.x);
            float vc = fmaf(fr, Cv.y, Cv.x);
            float vd = fmaf(fr, Dv.y, Dv.x);
            float fw = fwp[px];
            float top = fmaf(fw, vb - va, va);
            float bot = fmaf(fw, vd - vc, vc);
            float rv = fmaf(fh, bot - top, top);
            rv = fminf(fmaxf(rv, 0.f), 1.f);
            if (px) res.y = rv; else res.x = rv;
        }
        *(float2*)(out + ib) = res;
    }
}

// --------------------------------- launch ----------------------------------
extern "C" void kernel_launch(void* const* d_in, const int* in_sizes, int n_in,
                              void* d_out, int out_size) {
    const float* img     = (const float*)d_in[0];
    const float* conv1_w = (const float*)d_in[1];
    const float* conv1_b = (const float*)d_in[2];
    const float* conv2_w = (const float*)d_in[3];
    const float* conv2_b = (const float*)d_in[4];
    const float* conv3_w = (const float*)d_in[5];
    const float* conv3_b = (const float*)d_in[6];
    const float* conv4_w = (const float*)d_in[7];
    const float* conv4_b = (const float*)d_in[8];
    const float* lin1_w  = (const float*)d_in[9];
    const float* lin1_b  = (const float*)d_in[10];
    const float* lin2_w  = (const float*)d_in[11];
    const float* lin2_b  = (const float*)d_in[12];
    const float* luts    = (const float*)d_in[13];
    float* out = (float*)d_out;

    float *px, *pc1, *pc2, *pc3, *pc4, *pfeat, *ph1, *pwT, *plp, *pcp, *pwr, *pG;
    cudaGetSymbolAddress((void**)&px, g_x);
    cudaGetSymbolAddress((void**)&pc1, g_c1);
    cudaGetSymbolAddress((void**)&pc2, g_c2);
    cudaGetSymbolAddress((void**)&pc3, g_c3);
    cudaGetSymbolAddress((void**)&pc4, g_c4);
    cudaGetSymbolAddress((void**)&pfeat, g_feat);
    cudaGetSymbolAddress((void**)&ph1, g_h1);
    cudaGetSymbolAddress((void**)&pwT, g_wT);
    cudaGetSymbolAddress((void**)&plp, g_lpart);
    cudaGetSymbolAddress((void**)&pcp, g_cpart);
    cudaGetSymbolAddress((void**)&pwr, g_wrep);
    cudaGetSymbolAddress((void**)&pG, g_G);

    cudaFuncSetAttribute(final_v4, cudaFuncAttributeMaxDynamicSharedMemorySize, 49152);

    // 0. merged prep: resize + tiled weight transposes
    prep2_kernel<<<1536 + 919, 256>>>(img, px, conv1_w, conv2_w, conv3_w,
                                      conv4_w, lin1_w, pwr, pwT);

    // 2-5. conv stack (wide-load conv_v8, split-K)
    conv_v8<3, 32, 256, true><<<dim3(256, 1), 128>>>(px, pwr + WR1_OFF, conv1_b, pc1, 3);

    conv_v8<8, 64, 128, false><<<dim3(64, 4), 256>>>(pc1, pwr + WR2_OFF, conv2_b, pcp, 32);
    reduce_silu4_kernel<<<512, 256>>>((const float4*)pcp, (float4*)pc2, 131072, 4);

    conv_v8<8, 128, 64, false><<<dim3(32, 8), 256>>>(pc2, pwr + WR3_OFF, conv3_b, pcp, 64);
    reduce_silu4_kernel<<<256, 256>>>((const float4*)pcp, (float4*)pc3, 65536, 8);

    conv_v8<8, 256, 32, false><<<dim3(16, 16), 256>>>(pc3, pwr + WR4_OFF, conv4_b, pcp, 128);
    reduce_silu4_kernel<<<128, 256>>>((const float4*)pcp, (float4*)pc4, 32768, 16);

    // 6. multi-scale avg pools (sub-warp sized)
    pool_v2_kernel<<<1152, 256>>>(pc1, pc2, pc3, pc4, pfeat);

    // 7. lin1 (480->128, 3x3 reflect, SiLU), split-K x30
    lin1_kernel<<<dim3(30, 8, 2), 128>>>(pfeat, pwT, plp);
    lin1_reduce_kernel<<<64, 256>>>(plp, lin1_b, ph1);

    // 8+9. fused lin2 + G table
    gprep2_kernel<<<48, 256>>>(ph1, lin2_w, lin2_b, luts, pG);

    // 10. final: 4-corner gather + clip (channel-split, 4 CTAs/SM)
    final_v4<<<dim3(64, 3, 2), 512, 49152>>>(img, pG, out);
}